// round 4
// baseline (speedup 1.0000x reference)
#include <cuda_runtime.h>

#define EPSF 1e-7f
#define P_TOT 900
#define NCH 144
#define COUT 32

// Scratch (no allocations allowed)
static __device__ float g_zz[P_TOT * NCH * COUT];   // [p][n][c]
static __device__ float g_rr[P_TOT * NCH * COUT];   // [p][n][c]
static __device__ float g_W3[NCH * COUT * 16];      // [n][c][j][k]

// W[(n*32+c)*16 + k*4 + j] -> W3[n*512 + c*16 + j*4 + k]
__global__ void __launch_bounds__(256) wtrans_kernel(const float* __restrict__ W) {
    int t = blockIdx.x * 256 + threadIdx.x;
    if (t < NCH * COUT * 16) {
        int j = t & 3, k = (t >> 2) & 3, c = (t >> 4) & 31, n = t >> 9;
        g_W3[n * 512 + c * 16 + j * 4 + k] = W[t];
    }
}

// One CTA per parent p, 256 threads.
// lane = c2 | (j<<2) | (ih<<4); warp w owns c = 4w+c2.
// Thread computes vote elements e = (2ih)*4+j and (2ih+1)*4+j for its c.
// mode 0: rr uniform, M+E.  mode 1: read rr, M+E.  mode 2: M only, outputs.
__global__ void __launch_bounds__(256, 4) me_kernel(
    const float* __restrict__ pose,
    const float* __restrict__ beta_a, const float* __restrict__ beta_v,
    float* __restrict__ out, int mode, float lambd)
{
    __shared__ float sA[NCH * 20];       // child poses, 20-float rows
    __shared__ float sRR[NCH * COUT];    // rr staged [n][c]
    __shared__ float sZZ[NCH * COUT];    // zz staged [n][c]

    const int p = blockIdx.x;
    const int t = threadIdx.x;
    const int lane = t & 31, w = t >> 5;
    const int pr = p / 30, pcl = p % 30;

    // gather child poses (float4)
    for (int idx = t; idx < NCH * 4; idx += 256) {
        int n = idx >> 2, vq = idx & 3;
        int k = n >> 4, ci = n & 15;
        int q = (pr + k / 3) * 32 + pcl + (k % 3);
        float4 val = reinterpret_cast<const float4*>(pose + q * 256 + ci * 16)[vq];
        *reinterpret_cast<float4*>(sA + n * 20 + vq * 4) = val;
    }
    if (mode > 0) {
        const float4* rrp = reinterpret_cast<const float4*>(g_rr + (size_t)p * (NCH * COUT));
        float4* dst = reinterpret_cast<float4*>(sRR);
        for (int idx = t; idx < NCH * COUT / 4; idx += 256) dst[idx] = rrp[idx];
    }
    __syncthreads();

    const int c2 = lane & 3, j = (lane >> 2) & 3, ih = lane >> 4;
    const int c = (w << 2) | c2;
    const int aoff = ih << 3;                 // i0*4
    const float* W3c = g_W3 + c * 16 + j * 4; // + n*512

    // ---- M step: serial accumulation over n, no cross-lane reductions ----
    float rs = 0.f, s0 = 0.f, s1 = 0.f, q0 = 0.f, q1 = 0.f;
#pragma unroll 4
    for (int n = 0; n < NCH; n++) {
        float rrn = (mode == 0) ? 0.03125f : sRR[n * 32 + c];
        float4 wv = *reinterpret_cast<const float4*>(W3c + n * 512);
        float4 a0 = *reinterpret_cast<const float4*>(sA + n * 20 + aoff);
        float4 a1 = *reinterpret_cast<const float4*>(sA + n * 20 + aoff + 4);
        float v0 = a0.x * wv.x + a0.y * wv.y + a0.z * wv.z + a0.w * wv.w;
        float v1 = a1.x * wv.x + a1.y * wv.y + a1.z * wv.z + a1.w * wv.w;
        rs += rrn;
        s0 += rrn * v0; q0 += rrn * v0 * v0;
        s1 += rrn * v1; q1 += rrn * v1 * v1;
    }
    const float inv = 1.f / rs;
    const float mean0 = s0 * inv, mean1 = s1 * inv;
    const float var0 = fmaxf(q0 * inv - mean0 * mean0, 1e-30f);
    const float var1 = fmaxf(q1 * inv - mean1 * mean1, 1e-30f);
    float l = __logf(sqrtf(var0) + EPSF) + __logf(sqrtf(var1) + EPSF);
    l += __shfl_xor_sync(0xffffffffu, l, 4);
    l += __shfl_xor_sync(0xffffffffu, l, 8);
    l += __shfl_xor_sync(0xffffffffu, l, 16);   // sum over 16 elements of c
    const float cost = 16.f * beta_v[c] + rs * l;
    const float act = 1.f / (1.f + __expf(-lambd * (beta_a[c] - cost)));

    if (mode == 2) {
        float* op = out + 28800 + (size_t)p * 512 + c * 16 + j;
        op[aoff]     = mean0;
        op[aoff + 4] = mean1;
        if (lane < 4) out[p * COUT + c] = act;
        return;
    }

    // ---- E step: recompute votes, reduce over e via shfl, stage zz ----
    const float y0 = 0.5f / var0, y1 = 0.5f / var1;
    const float zb = __logf(act + EPSF) - l;
#pragma unroll 4
    for (int n = 0; n < NCH; n++) {
        float4 wv = *reinterpret_cast<const float4*>(W3c + n * 512);
        float4 a0 = *reinterpret_cast<const float4*>(sA + n * 20 + aoff);
        float4 a1 = *reinterpret_cast<const float4*>(sA + n * 20 + aoff + 4);
        float v0 = a0.x * wv.x + a0.y * wv.y + a0.z * wv.z + a0.w * wv.w;
        float v1 = a1.x * wv.x + a1.y * wv.y + a1.z * wv.z + a1.w * wv.w;
        float d0 = v0 - mean0, d1 = v1 - mean1;
        float pe = d0 * d0 * y0 + d1 * d1 * y1;
        pe += __shfl_xor_sync(0xffffffffu, pe, 4);
        pe += __shfl_xor_sync(0xffffffffu, pe, 8);
        pe += __shfl_xor_sync(0xffffffffu, pe, 16);
        if (lane < 4) sZZ[n * 32 + c] = zb - pe;
    }
    __syncthreads();

    float4* zzp = reinterpret_cast<float4*>(g_zz + (size_t)p * (NCH * COUT));
    const float4* src = reinterpret_cast<const float4*>(sZZ);
    for (int idx = t; idx < NCH * COUT / 4; idx += 256) zzp[idx] = src[idx];
}

// Softmax over parent axis p for every (n,c) on layout [p][n][c].
// One block per n (144), 512 threads = 32 c x 16 p-stripes.
__global__ void __launch_bounds__(512) softmax_kernel()
{
    __shared__ float red[16 * 33];
    __shared__ float gv[32];
    const int n = blockIdx.x;
    const int t = threadIdx.x;
    const int c = t & 31, st = t >> 5;
    const int base = n * 32 + c;

    float m = -1e30f;
    for (int p = st; p < P_TOT; p += 16)
        m = fmaxf(m, g_zz[(size_t)p * 4608 + base]);
    red[st * 33 + c] = m;
    __syncthreads();
    if (t < 32) {
        float M = red[t];
#pragma unroll
        for (int i = 1; i < 16; i++) M = fmaxf(M, red[i * 33 + t]);
        gv[t] = M;
    }
    __syncthreads();
    const float M = gv[c];

    float s = 0.f;
    for (int p = st; p < P_TOT; p += 16)
        s += __expf(g_zz[(size_t)p * 4608 + base] - M);
    red[st * 33 + c] = s;
    __syncthreads();
    if (t < 32) {
        float S = 0.f;
#pragma unroll
        for (int i = 0; i < 16; i++) S += red[i * 33 + t];
        gv[t] = 1.f / S;
    }
    __syncthreads();
    const float Sinv = gv[c];

    for (int p = st; p < P_TOT; p += 16) {
        size_t idx = (size_t)p * 4608 + base;
        g_rr[idx] = __expf(g_zz[idx] - M) * Sinv;
    }
}

extern "C" void kernel_launch(void* const* d_in, const int* in_sizes, int n_in,
                              void* d_out, int out_size)
{
    const float* pose = (const float*)d_in[1];
    const float* W    = (const float*)d_in[2];
    const float* ba   = (const float*)d_in[3];
    const float* bv   = (const float*)d_in[4];
    float* out = (float*)d_out;

    wtrans_kernel<<<288, 256>>>(W);
    me_kernel<<<P_TOT, 256>>>(pose, ba, bv, out, 0, 0.0f);
    softmax_kernel<<<NCH, 512>>>();
    me_kernel<<<P_TOT, 256>>>(pose, ba, bv, out, 1, 0.0005f);
    softmax_kernel<<<NCH, 512>>>();
    me_kernel<<<P_TOT, 256>>>(pose, ba, bv, out, 2, 0.000975f);
}

// round 5
// speedup vs baseline: 1.2639x; 1.2639x over previous
#include <cuda_runtime.h>

#define EPSF 1e-7f
#define P_TOT 900
#define NCH 144
#define COUT 32

// Scratch (no allocations allowed)
static __device__ float g_zz[P_TOT * NCH * COUT];   // [p][n][c]
static __device__ float g_rr[P_TOT * NCH * COUT];   // [p][n][c]

// CTA = 128 threads = 4 warps = 2 parents; warp pair (half 0/1) splits the
// 144 children. lane = c (all 32 output capsules per warp). W is used in its
// native layout [n][c][k][j]: per n the warp reads a dense 2KB row.
__global__ void __launch_bounds__(128, 4) me_kernel(
    const float* __restrict__ pose, const float* __restrict__ W,
    const float* __restrict__ beta_a, const float* __restrict__ beta_v,
    float* __restrict__ out, int mode, float lambd)
{
    __shared__ float sA[2][NCH * 16];          // child poses per parent
    __shared__ float sPart[2][2][2][512];      // [par][half][s/q][e*32+c]
    __shared__ float sRs[2][2][32];            // [par][half][c]

    const int t = threadIdx.x;
    const int lane = t & 31, w = t >> 5;
    const int p0 = blockIdx.x * 2;

    // gather child poses for both parents (float4, 64B rows)
    for (int idx = t; idx < 2 * NCH * 4; idx += 128) {
        int par = idx / 576, r = idx - par * 576;
        int n = r >> 2, vq = r & 3;
        int p = p0 + par;
        int pr = p / 30, pcl = p % 30;
        int k = n >> 4, ci = n & 15;
        int q = (pr + k / 3) * 32 + pcl + (k % 3);
        float4 val = reinterpret_cast<const float4*>(pose + q * 256 + ci * 16)[vq];
        *reinterpret_cast<float4*>(&sA[par][n * 16 + vq * 4]) = val;
    }
    __syncthreads();

    const int par = w >> 1, half = w & 1;
    const int p = p0 + par;
    const int c = lane;
    const float* Ab = sA[par];
    const float* Wb = W + c * 16;                          // + n*512
    const float* rrb = g_rr + (size_t)p * 4608 + c;        // + n*32
    const int n0 = half * 72;

    // ---- M step: per-thread full 4x4 vote matrix, serial over 72 children
    float s[16], q[16];
#pragma unroll
    for (int e = 0; e < 16; e++) { s[e] = 0.f; q[e] = 0.f; }
    float rs = 0.f;

#pragma unroll 2
    for (int nn = 0; nn < 72; nn++) {
        const int n = n0 + nn;
        float rrn = (mode == 0) ? 0.03125f : __ldg(rrb + n * 32);
        const float4* Wp = reinterpret_cast<const float4*>(Wb + n * 512);
        float4 w0 = Wp[0], w1 = Wp[1], w2 = Wp[2], w3 = Wp[3];
        const float4* Ap = reinterpret_cast<const float4*>(Ab + n * 16);
        rs += rrn;
#pragma unroll
        for (int i = 0; i < 4; i++) {
            float4 a = Ap[i];
            float vx = a.x * w0.x + a.y * w1.x + a.z * w2.x + a.w * w3.x;
            float vy = a.x * w0.y + a.y * w1.y + a.z * w2.y + a.w * w3.y;
            float vz = a.x * w0.z + a.y * w1.z + a.z * w2.z + a.w * w3.z;
            float vw = a.x * w0.w + a.y * w1.w + a.z * w2.w + a.w * w3.w;
            s[i*4+0] += rrn * vx; q[i*4+0] += rrn * vx * vx;
            s[i*4+1] += rrn * vy; q[i*4+1] += rrn * vy * vy;
            s[i*4+2] += rrn * vz; q[i*4+2] += rrn * vz * vz;
            s[i*4+3] += rrn * vw; q[i*4+3] += rrn * vw * vw;
        }
    }
    // exchange partials between the two halves of this parent
#pragma unroll
    for (int e = 0; e < 16; e++) {
        sPart[par][half][0][e * 32 + lane] = s[e];
        sPart[par][half][1][e * 32 + lane] = q[e];
    }
    sRs[par][half][lane] = rs;
    __syncthreads();

    const float rs_t = sRs[par][0][lane] + sRs[par][1][lane];
    const float inv = 1.f / rs_t;
    float mean[16], i2v[16];
    float l = 0.f;
#pragma unroll
    for (int e = 0; e < 16; e++) {
        float se = sPart[par][0][0][e * 32 + lane] + sPart[par][1][0][e * 32 + lane];
        float qe = sPart[par][0][1][e * 32 + lane] + sPart[par][1][1][e * 32 + lane];
        float m = se * inv;
        mean[e] = m;
        float var = fmaxf(qe * inv - m * m, 1e-30f);
        l += __logf(sqrtf(var) + EPSF);
        i2v[e] = 0.5f / var;
    }
    const float cost = 16.f * beta_v[c] + rs_t * l;
    const float act = 1.f / (1.f + __expf(-lambd * (beta_a[c] - cost)));

    if (mode == 2) {
        if (half == 0) {
            out[p * COUT + c] = act;
            float4* op = reinterpret_cast<float4*>(out + 28800 + (size_t)p * 512 + c * 16);
#pragma unroll
            for (int i = 0; i < 4; i++) {
                float4 m4 = { mean[i*4+0], mean[i*4+1], mean[i*4+2], mean[i*4+3] };
                op[i] = m4;
            }
        }
        return;
    }

    // ---- E step: recompute votes on this half, thread-local pe, direct STG
    const float zb = __logf(act + EPSF) - l;
    float* zzb = g_zz + (size_t)p * 4608 + c;
#pragma unroll 2
    for (int nn = 0; nn < 72; nn++) {
        const int n = n0 + nn;
        const float4* Wp = reinterpret_cast<const float4*>(Wb + n * 512);
        float4 w0 = Wp[0], w1 = Wp[1], w2 = Wp[2], w3 = Wp[3];
        const float4* Ap = reinterpret_cast<const float4*>(Ab + n * 16);
        float pe = 0.f;
#pragma unroll
        for (int i = 0; i < 4; i++) {
            float4 a = Ap[i];
            float vx = a.x * w0.x + a.y * w1.x + a.z * w2.x + a.w * w3.x;
            float vy = a.x * w0.y + a.y * w1.y + a.z * w2.y + a.w * w3.y;
            float vz = a.x * w0.z + a.y * w1.z + a.z * w2.z + a.w * w3.z;
            float vw = a.x * w0.w + a.y * w1.w + a.z * w2.w + a.w * w3.w;
            float d;
            d = vx - mean[i*4+0]; pe += d * d * i2v[i*4+0];
            d = vy - mean[i*4+1]; pe += d * d * i2v[i*4+1];
            d = vz - mean[i*4+2]; pe += d * d * i2v[i*4+2];
            d = vw - mean[i*4+3]; pe += d * d * i2v[i*4+3];
        }
        zzb[n * 32] = zb - pe;
    }
}

// Softmax over parent axis p for every (n,c) on layout [p][n][c].
// One block per n (144), 512 threads = 32 c x 16 p-stripes.
__global__ void __launch_bounds__(512) softmax_kernel()
{
    __shared__ float red[16 * 33];
    __shared__ float gv[32];
    const int n = blockIdx.x;
    const int t = threadIdx.x;
    const int c = t & 31, st = t >> 5;
    const int base = n * 32 + c;

    float m = -1e30f;
    for (int p = st; p < P_TOT; p += 16)
        m = fmaxf(m, g_zz[(size_t)p * 4608 + base]);
    red[st * 33 + c] = m;
    __syncthreads();
    if (t < 32) {
        float M = red[t];
#pragma unroll
        for (int i = 1; i < 16; i++) M = fmaxf(M, red[i * 33 + t]);
        gv[t] = M;
    }
    __syncthreads();
    const float M = gv[c];

    float s = 0.f;
    for (int p = st; p < P_TOT; p += 16)
        s += __expf(g_zz[(size_t)p * 4608 + base] - M);
    red[st * 33 + c] = s;
    __syncthreads();
    if (t < 32) {
        float S = 0.f;
#pragma unroll
        for (int i = 0; i < 16; i++) S += red[i * 33 + t];
        gv[t] = 1.f / S;
    }
    __syncthreads();
    const float Sinv = gv[c];

    for (int p = st; p < P_TOT; p += 16) {
        size_t idx = (size_t)p * 4608 + base;
        g_rr[idx] = __expf(g_zz[idx] - M) * Sinv;
    }
}

extern "C" void kernel_launch(void* const* d_in, const int* in_sizes, int n_in,
                              void* d_out, int out_size)
{
    const float* pose = (const float*)d_in[1];
    const float* W    = (const float*)d_in[2];
    const float* ba   = (const float*)d_in[3];
    const float* bv   = (const float*)d_in[4];
    float* out = (float*)d_out;

    me_kernel<<<450, 128>>>(pose, W, ba, bv, out, 0, 0.0f);
    softmax_kernel<<<NCH, 512>>>();
    me_kernel<<<450, 128>>>(pose, W, ba, bv, out, 1, 0.0005f);
    softmax_kernel<<<NCH, 512>>>();
    me_kernel<<<450, 128>>>(pose, W, ba, bv, out, 2, 0.000975f);
}